// round 16
// baseline (speedup 1.0000x reference)
#include <cuda_runtime.h>
#include <cuda_fp16.h>
#include <math.h>
#include <stdint.h>

#define N_INST 512
#define L      512
#define VOCAB  50000
#define EMB    128
#define NF     128
#define HID    384
#define ATT    128
#define NCLS   53
#define NHB    128         // h_bag partial blocks (4 instances each)

// ---------------- scratch (static device globals; no runtime alloc) ---------
__device__ int8_t g_A8[(size_t)VOCAB * EMB];        // emb int8 (per-row scale)
__device__ float  g_sA[VOCAB];
__device__ int8_t g_B8[HID * EMB];                  // B int8 [c][e], per-c scale
__device__ float  g_sB[HID];
__device__ float  g_Wt[HID * ATT];                  // Ww transposed fp32: [h][a]
__device__ __half g_projh[(size_t)VOCAB * HID];     // [v][c] fp16
__device__ float g_H[N_INST * HID];
__device__ float g_scores[N_INST];
__device__ float g_hbp[NHB * HID];                  // h_bag partials

// ---------------- prep A: quantize emb rows to int8 ------------------------
__global__ __launch_bounds__(256) void k_prep_A(const float* __restrict__ emb) {
    int w = (blockIdx.x * 256 + threadIdx.x) >> 5;   // global warp = row
    int lane = threadIdx.x & 31;
    if (w >= VOCAB) return;
    float4 v = *(const float4*)&emb[(size_t)w * EMB + lane * 4];
    float m = fmaxf(fmaxf(fabsf(v.x), fabsf(v.y)), fmaxf(fabsf(v.z), fabsf(v.w)));
#pragma unroll
    for (int off = 16; off; off >>= 1)
        m = fmaxf(m, __shfl_xor_sync(0xffffffffu, m, off));
    float inv = (m > 0.f) ? 127.f / m : 0.f;
    int q0 = __float2int_rn(v.x * inv), q1 = __float2int_rn(v.y * inv);
    int q2 = __float2int_rn(v.z * inv), q3 = __float2int_rn(v.w * inv);
    uint32_t p = (q0 & 0xff) | ((q1 & 0xff) << 8) | ((q2 & 0xff) << 16) | ((q3 & 0xff) << 24);
    *(uint32_t*)&g_A8[(size_t)w * EMB + lane * 4] = p;
    if (lane == 0) g_sA[w] = m * (1.f / 127.f);
}

// ---------------- prep misc: B int8 quant + Wt transpose --------------------
__global__ __launch_bounds__(256) void k_prep_misc(const float* __restrict__ conv_w,
                                                   const float* __restrict__ Ww) {
    if (blockIdx.x < 48) {                            // B quant: warp per c
        int c = blockIdx.x * 8 + (threadIdx.x >> 5);  // 48*8 = 384
        int lane = threadIdx.x & 31;
        int f = c & 127, kt = c >> 7;
        float v[4];
#pragma unroll
        for (int j = 0; j < 4; j++)
            v[j] = conv_w[(f * EMB + lane * 4 + j) * 3 + kt];
        float m = fmaxf(fmaxf(fabsf(v[0]), fabsf(v[1])), fmaxf(fabsf(v[2]), fabsf(v[3])));
#pragma unroll
        for (int off = 16; off; off >>= 1)
            m = fmaxf(m, __shfl_xor_sync(0xffffffffu, m, off));
        float inv = (m > 0.f) ? 127.f / m : 0.f;
        int q0 = __float2int_rn(v[0] * inv), q1 = __float2int_rn(v[1] * inv);
        int q2 = __float2int_rn(v[2] * inv), q3 = __float2int_rn(v[3] * inv);
        uint32_t p = (q0 & 0xff) | ((q1 & 0xff) << 8) | ((q2 & 0xff) << 16) | ((q3 & 0xff) << 24);
        *(uint32_t*)&g_B8[c * EMB + lane * 4] = p;
        if (lane == 0) g_sB[c] = m * (1.f / 127.f);
    } else {                                          // Wt transpose
        int j = (blockIdx.x - 48) * 256 + threadIdx.x;
        if (j < HID * ATT) {
            int h = j >> 7, a = j & 127;
            g_Wt[j] = Ww[a * HID + h];
        }
    }
}

// ---------------- K1: int8 IMMA proj GEMM, single A pass -------------------
#define SR8   144                     // int8 row stride (conflict-free, 16B-align)
#define CROW  136                     // half row stride for C staging
#define K1_A8   0
#define K1_B8   18432
#define K1_SAS  36864
#define K1_SBS  37376
#define K1_CS   37888
#define K1_SMEM (37888 + 128 * CROW * 2)   // 72704 B -> 2 CTAs/SM

#define MMA_S8(d, a, b) \
    asm volatile("mma.sync.aligned.m16n8k32.row.col.s32.s8.s8.s32 " \
        "{%0,%1,%2,%3}, {%4,%5,%6,%7}, {%8,%9}, {%0,%1,%2,%3};" \
        : "+r"(d[0]), "+r"(d[1]), "+r"(d[2]), "+r"(d[3]) \
        : "r"(a[0]), "r"(a[1]), "r"(a[2]), "r"(a[3]), "r"(b[0]), "r"(b[1]))

__global__ __launch_bounds__(256, 2) void k1_imma() {
    extern __shared__ char sm_[];
    int8_t* As8 = (int8_t*)(sm_ + K1_A8);
    int8_t* Bs8 = (int8_t*)(sm_ + K1_B8);
    float*  sAs = (float*)(sm_ + K1_SAS);
    float*  sBs = (float*)(sm_ + K1_SBS);
    __half* Cs  = (__half*)(sm_ + K1_CS);

    int tid = threadIdx.x;
    int m0 = blockIdx.x * 128;

    // ---- A: int8 rows + scales (zero past VOCAB) ----
    for (int i = tid; i < 1024; i += 256) {           // 128 rows x 8 int4
        int row = i >> 3, seg = i & 7;
        int gm = m0 + row;
        int4 va = make_int4(0, 0, 0, 0);
        if (gm < VOCAB) va = *(const int4*)&g_A8[(size_t)gm * EMB + seg * 16];
        *(int4*)&As8[row * SR8 + seg * 16] = va;
    }
    if (tid < 128) {
        int gm = m0 + tid;
        sAs[tid] = (gm < VOCAB) ? g_sA[gm] : 0.f;
    }

    int lane = tid & 31, g = lane >> 2, t = lane & 3;
    int wid = tid >> 5;
    int mbase = (wid & 3) * 32;
    int nbase = (wid >> 2) * 64;

    for (int nb = 0; nb < 3; nb++) {
        // ---- B tile + scales ----
        for (int i = tid; i < 1024; i += 256) {
            int row = i >> 3, seg = i & 7;
            *(int4*)&Bs8[row * SR8 + seg * 16] =
                *(const int4*)&g_B8[(nb * 128 + row) * EMB + seg * 16];
        }
        if (tid < 128) sBs[tid] = g_sB[nb * 128 + tid];
        __syncthreads();

        int acc[2][8][4];
#pragma unroll
        for (int mi = 0; mi < 2; mi++)
#pragma unroll
            for (int nj = 0; nj < 8; nj++)
#pragma unroll
                for (int q = 0; q < 4; q++) acc[mi][nj][q] = 0;

#pragma unroll
        for (int ks = 0; ks < 4; ks++) {
            int k32 = ks * 32;
            uint32_t a[2][4], b[8][2];
#pragma unroll
            for (int mi = 0; mi < 2; mi++) {
                int r0 = mbase + mi * 16 + g;
                a[mi][0] = *(const uint32_t*)&As8[r0 * SR8 + k32 + t * 4];
                a[mi][1] = *(const uint32_t*)&As8[(r0 + 8) * SR8 + k32 + t * 4];
                a[mi][2] = *(const uint32_t*)&As8[r0 * SR8 + k32 + 16 + t * 4];
                a[mi][3] = *(const uint32_t*)&As8[(r0 + 8) * SR8 + k32 + 16 + t * 4];
            }
#pragma unroll
            for (int nj = 0; nj < 8; nj++) {
                int n0i = nbase + nj * 8 + g;
                b[nj][0] = *(const uint32_t*)&Bs8[n0i * SR8 + k32 + t * 4];
                b[nj][1] = *(const uint32_t*)&Bs8[n0i * SR8 + k32 + 16 + t * 4];
            }
#pragma unroll
            for (int mi = 0; mi < 2; mi++)
#pragma unroll
                for (int nj = 0; nj < 8; nj++) MMA_S8(acc[mi][nj], a[mi], b[nj]);
        }
        __syncthreads();                              // B8/A8 LDS complete

        // ---- dequant + stage C (half) ----
#pragma unroll
        for (int mi = 0; mi < 2; mi++) {
            int r = mbase + mi * 16 + g;
            float sa0 = sAs[r], sa1 = sAs[r + 8];
#pragma unroll
            for (int nj = 0; nj < 8; nj++) {
                int cc = nbase + nj * 8 + t * 2;
                float sb0 = sBs[cc], sb1 = sBs[cc + 1];
                __half2 h0 = __floats2half2_rn((float)acc[mi][nj][0] * sa0 * sb0,
                                               (float)acc[mi][nj][1] * sa0 * sb1);
                __half2 h1 = __floats2half2_rn((float)acc[mi][nj][2] * sa1 * sb0,
                                               (float)acc[mi][nj][3] * sa1 * sb1);
                *(__half2*)&Cs[r * CROW + cc]       = h0;
                *(__half2*)&Cs[(r + 8) * CROW + cc] = h1;
            }
        }
        __syncthreads();
        {
            int row = tid >> 1, seg = tid & 1;
            int gm = m0 + row;
            if (gm < VOCAB) {
                const int4* src = (const int4*)&Cs[row * CROW + seg * 64];
                int4* dst = (int4*)&g_projh[(size_t)gm * HID + nb * 128 + seg * 64];
#pragma unroll
                for (int j = 0; j < 8; j++) dst[j] = src[j];
            }
        }
        __syncthreads();                              // Cs reads done before next stage
    }
}

// ---------------- K2: gather + pool + fused scores, 2 inst/block -----------
#define SPAD 8
__global__ __launch_bounds__(512) void k2_pool(const int* __restrict__ ids_g,
                                               const int* __restrict__ pe1,
                                               const int* __restrict__ pe2,
                                               const float* __restrict__ conv_b,
                                               const float* __restrict__ Wb,
                                               const float* __restrict__ u) {
    int n0 = blockIdx.x * 2;
    int tid = threadIdx.x;
    int f8 = tid & 15, part = (tid >> 4) & 15, inst = tid >> 8;
    __shared__ int S[2][L + 2 + SPAD];
    __shared__ uint4 pb[2][3][16][16];
    __shared__ __align__(16) float Hsm[2][HID];
    __shared__ __align__(16) float partial[2][4][128];
    __shared__ float red[2][4];

    for (int i = tid; i < 2 * L; i += 512) {
        int ii = i >> 9, l = i & 511;
        S[ii][l + 1] = ids_g[(n0 + ii) * L + l] * (HID * 2);
    }
    if (tid < 2) {
        S[tid][0] = 0;
#pragma unroll
        for (int j = 0; j <= SPAD; j++) S[tid][L + 1 + j] = 0;
    }
    __syncthreads();

    int p1 = pe1[n0 + inst], p2 = pe2[n0 + inst];
    int e1 = min(p1, p2), e2 = max(p1, p2);
    e1 = max(0, min(e1, L));
    e2 = max(0, min(e2, L));
    if (e1 == e2) e2 = min(e1 + 1, L);
    int end1 = (e1 > 0) ? e1 : 1;

    __half2 hb[4];
#pragma unroll
    for (int j = 0; j < 4; j++)
        hb[j] = __floats2half2_rn(conv_b[8 * f8 + 2 * j], conv_b[8 * f8 + 2 * j + 1]);
    __half2 zz = __floats2half2_rn(0.f, 0.f);
    __half2 m1[4] = {zz, zz, zz, zz}, m2[4] = {zz, zz, zz, zz}, m3[4] = {zz, zz, zz, zz};

    const char* base = (const char*)g_projh;
    int coff = f8 * 16;
    int t0 = part * 32;
    const int* Si = S[inst];

    int sw[6];
#pragma unroll
    for (int j = 0; j < 6; j++) sw[j] = Si[t0 + j];

#pragma unroll 2
    for (int bs = t0; bs < t0 + 32; bs += 4) {
        int sn0 = Si[bs + 6], sn1 = Si[bs + 7], sn2 = Si[bs + 8], sn3 = Si[bs + 9];
#pragma unroll
        for (int j = 0; j < 4; j++) {
            int l = bs + j;
            uint4 v0 = *(const uint4*)(base + sw[j]     + coff);
            uint4 v1 = *(const uint4*)(base + sw[j + 1] + 256 + coff);
            uint4 v2 = *(const uint4*)(base + sw[j + 2] + 512 + coff);
            __half2 s[4];
            s[0] = __hadd2(__hadd2(*(__half2*)&v0.x, *(__half2*)&v1.x),
                           __hadd2(*(__half2*)&v2.x, hb[0]));
            s[1] = __hadd2(__hadd2(*(__half2*)&v0.y, *(__half2*)&v1.y),
                           __hadd2(*(__half2*)&v2.y, hb[1]));
            s[2] = __hadd2(__hadd2(*(__half2*)&v0.z, *(__half2*)&v1.z),
                           __hadd2(*(__half2*)&v2.z, hb[2]));
            s[3] = __hadd2(__hadd2(*(__half2*)&v0.w, *(__half2*)&v1.w),
                           __hadd2(*(__half2*)&v2.w, hb[3]));
            bool in1 = (l < end1);
            bool in2 = (l >= e1 && l < e2);
            bool in3 = (e2 < L) ? (l >= e2) : (l == L - 1);
#pragma unroll
            for (int q = 0; q < 4; q++) {
                if (in1) m1[q] = __hmax2(m1[q], s[q]);
                if (in2) m2[q] = __hmax2(m2[q], s[q]);
                if (in3) m3[q] = __hmax2(m3[q], s[q]);
            }
        }
        sw[0] = sw[4]; sw[1] = sw[5];
        sw[2] = sn0; sw[3] = sn1; sw[4] = sn2; sw[5] = sn3;
    }
    pb[inst][0][part][f8] = make_uint4(*(uint32_t*)&m1[0], *(uint32_t*)&m1[1],
                                       *(uint32_t*)&m1[2], *(uint32_t*)&m1[3]);
    pb[inst][1][part][f8] = make_uint4(*(uint32_t*)&m2[0], *(uint32_t*)&m2[1],
                                       *(uint32_t*)&m2[2], *(uint32_t*)&m2[3]);
    pb[inst][2][part][f8] = make_uint4(*(uint32_t*)&m3[0], *(uint32_t*)&m3[1],
                                       *(uint32_t*)&m3[2], *(uint32_t*)&m3[3]);
    __syncthreads();

    if (tid < 96) {
        int ii = tid / 48, r = tid % 48;
        int seg = r >> 4, fm = r & 15;
        __half2 r0 = zz, r1 = zz, r2 = zz, r3 = zz;
#pragma unroll
        for (int q = 0; q < 16; q++) {
            uint4 v = pb[ii][seg][q][fm];
            r0 = __hmax2(r0, *(__half2*)&v.x);
            r1 = __hmax2(r1, *(__half2*)&v.y);
            r2 = __hmax2(r2, *(__half2*)&v.z);
            r3 = __hmax2(r3, *(__half2*)&v.w);
        }
        float2 a0 = __half22float2(r0), a1 = __half22float2(r1);
        float2 a2 = __half22float2(r2), a3 = __half22float2(r3);
        float4 hv0 = make_float4(a0.x, a0.y, a1.x, a1.y);
        float4 hv1 = make_float4(a2.x, a2.y, a3.x, a3.y);
        int off = seg * 128 + 8 * fm;
        *(float4*)&g_H[(n0 + ii) * HID + off]     = hv0;
        *(float4*)&g_H[(n0 + ii) * HID + off + 4] = hv1;
        *(float4*)&Hsm[ii][off]     = hv0;
        *(float4*)&Hsm[ii][off + 4] = hv1;
    }
    __syncthreads();

    {
        int a = tid & 127, hg = tid >> 7;
        float acc0 = 0.f, acc1 = 0.f;
        const float* W = g_Wt + a;
        int h0 = hg * 96;
#pragma unroll 8
        for (int h = h0; h < h0 + 96; h++) {
            float wv = __ldg(W + h * ATT);
            acc0 += Hsm[0][h] * wv;
            acc1 += Hsm[1][h] * wv;
        }
        partial[0][hg][a] = acc0;
        partial[1][hg][a] = acc1;
    }
    __syncthreads();
    if (tid < 256) {
        int ii = tid >> 7, a = tid & 127;
        float s = partial[ii][0][a] + partial[ii][1][a] +
                  partial[ii][2][a] + partial[ii][3][a];
        float e = tanhf(s + __ldg(&Wb[a])) * __ldg(&u[a]);
#pragma unroll
        for (int off = 16; off; off >>= 1)
            e += __shfl_down_sync(0xffffffffu, e, off);
        if ((tid & 31) == 0) red[ii][(tid >> 5) & 3] = e;
    }
    __syncthreads();
    if (tid < 2)
        g_scores[n0 + tid] = red[tid][0] + red[tid][1] + red[tid][2] + red[tid][3];
}

// ---------------- softmax helper (no max subtraction; |s| <= ~9) -----------
__device__ __forceinline__ float block_softmax_512(int tid, float* attn_s,
                                                   float* red16) {
    float e = expf(g_scores[tid]);
    float sv = e;
#pragma unroll
    for (int off = 16; off; off >>= 1)
        sv += __shfl_xor_sync(0xffffffffu, sv, off);
    if ((tid & 31) == 0) red16[tid >> 5] = sv;
    __syncthreads();
    __shared__ float bsum;
    if (tid == 0) {
        float t = 0.f;
        for (int i = 0; i < 16; i++) t += red16[i];
        bsum = t;
    }
    __syncthreads();
    float a = e / bsum;
    attn_s[tid] = a;
    __syncthreads();
    return a;
}

// ---------------- K4: h_bag partials (128 blocks x 4 instances) ------------
__global__ __launch_bounds__(512) void k4_hbag() {
    int tid = threadIdx.x;
    int b = blockIdx.x;
    __shared__ float attn_s[N_INST];
    __shared__ float red16[16];
    block_softmax_512(tid, attn_s, red16);

    if (tid < HID) {
        int n0 = b * 4;
        float acc = 0.f;
#pragma unroll
        for (int j = 0; j < 4; j++)
            acc += attn_s[n0 + j] * g_H[(n0 + j) * HID + tid];
        g_hbp[b * HID + tid] = acc;
    }
}

// ---------------- K5: attn out + hb sum + logits ---------------------------
__global__ __launch_bounds__(512) void k5_out(const float* __restrict__ fc_w,
                                              const float* __restrict__ fc_b,
                                              float* __restrict__ out) {
    int tid = threadIdx.x;
    __shared__ float attn_s[N_INST];
    __shared__ float red16[16];
    __shared__ float hb[HID];

    float a = block_softmax_512(tid, attn_s, red16);
    out[NCLS + tid] = a;

    if (tid < HID) {
        float acc = 0.f;
#pragma unroll 16
        for (int b = 0; b < NHB; b++)
            acc += g_hbp[b * HID + tid];
        hb[tid] = acc;
    }
    __syncthreads();

    int w = tid >> 5, lane = tid & 31;
    for (int t = w; t < NCLS; t += 16) {
        float part = 0.f;
#pragma unroll
        for (int c = lane; c < HID; c += 32)
            part += hb[c] * __ldg(&fc_w[t * HID + c]);
#pragma unroll
        for (int off = 16; off; off >>= 1)
            part += __shfl_down_sync(0xffffffffu, part, off);
        if (lane == 0) out[t] = part + fc_b[t];
    }
}

// ---------------- launch ------------------------------------------------------
extern "C" void kernel_launch(void* const* d_in, const int* in_sizes, int n_in,
                              void* d_out, int out_size) {
    const int*   char_ids = (const int*)d_in[0];
    const int*   pe1      = (const int*)d_in[1];
    const int*   pe2      = (const int*)d_in[2];
    const float* emb      = (const float*)d_in[3];
    const float* conv_w   = (const float*)d_in[4];
    const float* conv_b   = (const float*)d_in[5];
    const float* W_w      = (const float*)d_in[6];
    const float* W_b      = (const float*)d_in[7];
    const float* u_w      = (const float*)d_in[8];
    const float* fc_w     = (const float*)d_in[9];
    const float* fc_b     = (const float*)d_in[10];
    float* out = (float*)d_out;

    static bool attr_set = false;
    if (!attr_set) {
        cudaFuncSetAttribute(k1_imma, cudaFuncAttributeMaxDynamicSharedMemorySize, K1_SMEM);
        attr_set = true;
    }

    k_prep_A<<<(VOCAB * 32 + 255) / 256, 256>>>(emb);
    k_prep_misc<<<48 + (HID * ATT + 255) / 256, 256>>>(conv_w, W_w);
    k1_imma<<<(VOCAB + 127) / 128, 256, K1_SMEM>>>();
    k2_pool<<<N_INST / 2, 512>>>(char_ids, pe1, pe2, conv_b, W_b, u_w);
    k4_hbag<<<NHB, 512>>>();
    k5_out<<<1, 512>>>(fc_w, fc_b, out);
}

// round 17
// speedup vs baseline: 1.3921x; 1.3921x over previous
#include <cuda_runtime.h>
#include <cuda_fp16.h>
#include <math.h>
#include <stdint.h>

#define N_INST 512
#define L      512
#define VOCAB  50000
#define EMB    128
#define NF     128
#define HID    384
#define ATT    128
#define NCLS   53
#define NHB    128         // h_bag partial blocks (4 instances each)

// ---------------- scratch (static device globals; no runtime alloc) ---------
__device__ __half g_Bf[HID * EMB];                  // [c][e] fp16, c = kt*128+f
__device__ float  g_Wt[HID * ATT];                  // Ww transposed fp32: [h][a]
__device__ __half g_projh[(size_t)VOCAB * HID];     // [v][c] fp16
__device__ float g_H[N_INST * HID];
__device__ float g_scores[N_INST];
__device__ float g_hbp[NHB * HID];                  // h_bag partials
__device__ unsigned g_ticket = 0;                   // k45 completion counter

// ---------------- prep: B transpose (fp16) + Ww transpose (fp32) -----------
__global__ void k_prep(const float* __restrict__ conv_w, const float* __restrict__ Ww) {
    int idx = blockIdx.x * blockDim.x + threadIdx.x;
    if (idx < HID * EMB) {
        int c = idx >> 7, e = idx & 127;
        int f = c & 127, kt = c >> 7;
        g_Bf[c * EMB + e] = __float2half(conv_w[(f * EMB + e) * 3 + kt]);
    } else if (idx < 2 * HID * EMB) {
        int j = idx - HID * EMB;            // j = h*128 + a
        int h = j >> 7, a = j & 127;
        g_Wt[j] = Ww[a * HID + h];
    }
}

// ---------------- K1: fp16-acc mma.sync proj GEMM, single A pass -----------
#define SROW 136                      // padded half row stride (272 B)
#define K1_SMEM (2 * 128 * SROW * 2)  // 69632 B -> 3 CTAs/SM

#define MMA_F16ACC(d, a, b) \
    asm volatile("mma.sync.aligned.m16n8k16.row.col.f16.f16.f16.f16 " \
        "{%0,%1}, {%2,%3,%4,%5}, {%6,%7}, {%0,%1};" \
        : "+r"(d[0]), "+r"(d[1]) \
        : "r"(a[0]), "r"(a[1]), "r"(a[2]), "r"(a[3]), "r"(b[0]), "r"(b[1]))

__global__ __launch_bounds__(256, 3) void k1_hmma(const float* __restrict__ emb) {
    extern __shared__ __half sm_[];
    __half* As = sm_;
    __half* Bs = sm_ + 128 * SROW;     // doubles as C staging after compute

    int tid = threadIdx.x;
    int m0 = blockIdx.x * 128;

    for (int i = tid; i < 2048; i += 256) {          // 128 rows x 16 chunks of 8
        int row = i >> 4, k = (i & 15) * 8;
        int gm = m0 + row;
        uint2 p0 = make_uint2(0u, 0u), p1 = make_uint2(0u, 0u);
        if (gm < VOCAB) {
            float4 f0 = *(const float4*)&emb[(size_t)gm * EMB + k];
            float4 f1 = *(const float4*)&emb[(size_t)gm * EMB + k + 4];
            __half2 h0 = __floats2half2_rn(f0.x, f0.y);
            __half2 h1 = __floats2half2_rn(f0.z, f0.w);
            __half2 h2 = __floats2half2_rn(f1.x, f1.y);
            __half2 h3 = __floats2half2_rn(f1.z, f1.w);
            p0 = make_uint2(*(uint32_t*)&h0, *(uint32_t*)&h1);
            p1 = make_uint2(*(uint32_t*)&h2, *(uint32_t*)&h3);
        }
        *(uint2*)&As[row * SROW + k]     = p0;
        *(uint2*)&As[row * SROW + k + 4] = p1;
    }

    int lane = tid & 31, g = lane >> 2, t = lane & 3;
    int wid = tid >> 5;
    int mbase = (wid & 3) * 32;
    int nbase = (wid >> 2) * 64;

    for (int nb = 0; nb < 3; nb++) {
        for (int i = tid; i < 2048; i += 256) {
            int row = i >> 4, k = (i & 15) * 8;
            *(int4*)&Bs[row * SROW + k] =
                *(const int4*)&g_Bf[(nb * 128 + row) * EMB + k];
        }
        __syncthreads();

        uint32_t acc[2][8][2];
#pragma unroll
        for (int mi = 0; mi < 2; mi++)
#pragma unroll
            for (int nj = 0; nj < 8; nj++) { acc[mi][nj][0] = 0u; acc[mi][nj][1] = 0u; }

#pragma unroll
        for (int ks = 0; ks < 8; ks++) {
            int k16 = ks * 16;
            uint32_t a[2][4], b[8][2];
#pragma unroll
            for (int mi = 0; mi < 2; mi++) {
                int r0 = mbase + mi * 16 + g;
                a[mi][0] = *(const uint32_t*)&As[r0 * SROW + k16 + t * 2];
                a[mi][1] = *(const uint32_t*)&As[(r0 + 8) * SROW + k16 + t * 2];
                a[mi][2] = *(const uint32_t*)&As[r0 * SROW + k16 + 8 + t * 2];
                a[mi][3] = *(const uint32_t*)&As[(r0 + 8) * SROW + k16 + 8 + t * 2];
            }
#pragma unroll
            for (int nj = 0; nj < 8; nj++) {
                int n0i = nbase + nj * 8 + g;
                b[nj][0] = *(const uint32_t*)&Bs[n0i * SROW + k16 + t * 2];
                b[nj][1] = *(const uint32_t*)&Bs[n0i * SROW + k16 + 8 + t * 2];
            }
#pragma unroll
            for (int mi = 0; mi < 2; mi++)
#pragma unroll
                for (int nj = 0; nj < 8; nj++) MMA_F16ACC(acc[mi][nj], a[mi], b[nj]);
        }
        __syncthreads();

#pragma unroll
        for (int mi = 0; mi < 2; mi++)
#pragma unroll
            for (int nj = 0; nj < 8; nj++) {
                int r = mbase + mi * 16 + g;
                int cc = nbase + nj * 8 + t * 2;
                *(uint32_t*)&Bs[r * SROW + cc]       = acc[mi][nj][0];
                *(uint32_t*)&Bs[(r + 8) * SROW + cc] = acc[mi][nj][1];
            }
        __syncthreads();
        {
            int row = tid >> 1, seg = tid & 1;
            int gm = m0 + row;
            if (gm < VOCAB) {
                const int4* src = (const int4*)&Bs[row * SROW + seg * 64];
                int4* dst = (int4*)&g_projh[(size_t)gm * HID + nb * 128 + seg * 64];
#pragma unroll
                for (int j = 0; j < 8; j++) dst[j] = src[j];
            }
        }
        __syncthreads();
    }
}

// ---------------- K2: gather + pool + fused scores, 2 inst/block -----------
#define SPAD 8
__global__ __launch_bounds__(512) void k2_pool(const int* __restrict__ ids_g,
                                               const int* __restrict__ pe1,
                                               const int* __restrict__ pe2,
                                               const float* __restrict__ conv_b,
                                               const float* __restrict__ Wb,
                                               const float* __restrict__ u) {
    int n0 = blockIdx.x * 2;
    int tid = threadIdx.x;
    int f8 = tid & 15, part = (tid >> 4) & 15, inst = tid >> 8;
    __shared__ int S[2][L + 2 + SPAD];
    __shared__ uint4 pb[2][3][16][16];
    __shared__ __align__(16) float Hsm[2][HID];
    __shared__ __align__(16) float partial[2][4][128];
    __shared__ float red[2][4];

    for (int i = tid; i < 2 * L; i += 512) {
        int ii = i >> 9, l = i & 511;
        S[ii][l + 1] = ids_g[(n0 + ii) * L + l] * (HID * 2);
    }
    if (tid < 2) {
        S[tid][0] = 0;
#pragma unroll
        for (int j = 0; j <= SPAD; j++) S[tid][L + 1 + j] = 0;
    }
    __syncthreads();

    int p1 = pe1[n0 + inst], p2 = pe2[n0 + inst];
    int e1 = min(p1, p2), e2 = max(p1, p2);
    e1 = max(0, min(e1, L));
    e2 = max(0, min(e2, L));
    if (e1 == e2) e2 = min(e1 + 1, L);
    int end1 = (e1 > 0) ? e1 : 1;

    __half2 hb[4];
#pragma unroll
    for (int j = 0; j < 4; j++)
        hb[j] = __floats2half2_rn(conv_b[8 * f8 + 2 * j], conv_b[8 * f8 + 2 * j + 1]);
    __half2 zz = __floats2half2_rn(0.f, 0.f);
    __half2 m1[4] = {zz, zz, zz, zz}, m2[4] = {zz, zz, zz, zz}, m3[4] = {zz, zz, zz, zz};

    const char* base = (const char*)g_projh;
    int coff = f8 * 16;
    int t0 = part * 32;
    const int* Si = S[inst];

    int sw[6];
#pragma unroll
    for (int j = 0; j < 6; j++) sw[j] = Si[t0 + j];

#pragma unroll 2
    for (int bs = t0; bs < t0 + 32; bs += 4) {
        int sn0 = Si[bs + 6], sn1 = Si[bs + 7], sn2 = Si[bs + 8], sn3 = Si[bs + 9];
#pragma unroll
        for (int j = 0; j < 4; j++) {
            int l = bs + j;
            uint4 v0 = *(const uint4*)(base + sw[j]     + coff);
            uint4 v1 = *(const uint4*)(base + sw[j + 1] + 256 + coff);
            uint4 v2 = *(const uint4*)(base + sw[j + 2] + 512 + coff);
            __half2 s[4];
            s[0] = __hadd2(__hadd2(*(__half2*)&v0.x, *(__half2*)&v1.x),
                           __hadd2(*(__half2*)&v2.x, hb[0]));
            s[1] = __hadd2(__hadd2(*(__half2*)&v0.y, *(__half2*)&v1.y),
                           __hadd2(*(__half2*)&v2.y, hb[1]));
            s[2] = __hadd2(__hadd2(*(__half2*)&v0.z, *(__half2*)&v1.z),
                           __hadd2(*(__half2*)&v2.z, hb[2]));
            s[3] = __hadd2(__hadd2(*(__half2*)&v0.w, *(__half2*)&v1.w),
                           __hadd2(*(__half2*)&v2.w, hb[3]));
            bool in1 = (l < end1);
            bool in2 = (l >= e1 && l < e2);
            bool in3 = (e2 < L) ? (l >= e2) : (l == L - 1);
#pragma unroll
            for (int q = 0; q < 4; q++) {
                if (in1) m1[q] = __hmax2(m1[q], s[q]);
                if (in2) m2[q] = __hmax2(m2[q], s[q]);
                if (in3) m3[q] = __hmax2(m3[q], s[q]);
            }
        }
        sw[0] = sw[4]; sw[1] = sw[5];
        sw[2] = sn0; sw[3] = sn1; sw[4] = sn2; sw[5] = sn3;
    }
    pb[inst][0][part][f8] = make_uint4(*(uint32_t*)&m1[0], *(uint32_t*)&m1[1],
                                       *(uint32_t*)&m1[2], *(uint32_t*)&m1[3]);
    pb[inst][1][part][f8] = make_uint4(*(uint32_t*)&m2[0], *(uint32_t*)&m2[1],
                                       *(uint32_t*)&m2[2], *(uint32_t*)&m2[3]);
    pb[inst][2][part][f8] = make_uint4(*(uint32_t*)&m3[0], *(uint32_t*)&m3[1],
                                       *(uint32_t*)&m3[2], *(uint32_t*)&m3[3]);
    __syncthreads();

    if (tid < 96) {
        int ii = tid / 48, r = tid % 48;
        int seg = r >> 4, fm = r & 15;
        __half2 r0 = zz, r1 = zz, r2 = zz, r3 = zz;
#pragma unroll
        for (int q = 0; q < 16; q++) {
            uint4 v = pb[ii][seg][q][fm];
            r0 = __hmax2(r0, *(__half2*)&v.x);
            r1 = __hmax2(r1, *(__half2*)&v.y);
            r2 = __hmax2(r2, *(__half2*)&v.z);
            r3 = __hmax2(r3, *(__half2*)&v.w);
        }
        float2 a0 = __half22float2(r0), a1 = __half22float2(r1);
        float2 a2 = __half22float2(r2), a3 = __half22float2(r3);
        float4 hv0 = make_float4(a0.x, a0.y, a1.x, a1.y);
        float4 hv1 = make_float4(a2.x, a2.y, a3.x, a3.y);
        int off = seg * 128 + 8 * fm;
        *(float4*)&g_H[(n0 + ii) * HID + off]     = hv0;
        *(float4*)&g_H[(n0 + ii) * HID + off + 4] = hv1;
        *(float4*)&Hsm[ii][off]     = hv0;
        *(float4*)&Hsm[ii][off + 4] = hv1;
    }
    __syncthreads();

    {
        int a = tid & 127, hg = tid >> 7;
        float acc0 = 0.f, acc1 = 0.f;
        const float* W = g_Wt + a;
        int h0 = hg * 96;
#pragma unroll 8
        for (int h = h0; h < h0 + 96; h++) {
            float wv = __ldg(W + h * ATT);
            acc0 += Hsm[0][h] * wv;
            acc1 += Hsm[1][h] * wv;
        }
        partial[0][hg][a] = acc0;
        partial[1][hg][a] = acc1;
    }
    __syncthreads();
    if (tid < 256) {
        int ii = tid >> 7, a = tid & 127;
        float s = partial[ii][0][a] + partial[ii][1][a] +
                  partial[ii][2][a] + partial[ii][3][a];
        float e = tanhf(s + __ldg(&Wb[a])) * __ldg(&u[a]);
#pragma unroll
        for (int off = 16; off; off >>= 1)
            e += __shfl_down_sync(0xffffffffu, e, off);
        if ((tid & 31) == 0) red[ii][(tid >> 5) & 3] = e;
    }
    __syncthreads();
    if (tid < 2)
        g_scores[n0 + tid] = red[tid][0] + red[tid][1] + red[tid][2] + red[tid][3];
}

// ---------------- K45: fused softmax + h_bag partials + final (ticket) -----
// 128 blocks. Each computes the (cheap) block-local softmax + a 4-instance
// h_bag partial, then takes a ticket; the LAST block sums partials, writes
// attn + logits, and resets the ticket (replay-deterministic).
__global__ __launch_bounds__(512) void k45(const float* __restrict__ fc_w,
                                           const float* __restrict__ fc_b,
                                           float* __restrict__ out) {
    int tid = threadIdx.x;
    int b = blockIdx.x;
    __shared__ float attn_s[N_INST];
    __shared__ float red16[16];
    __shared__ float bsum;
    __shared__ int islast;
    __shared__ float hbf[HID];

    // block-local softmax (no max subtraction; |s| <= ~9)
    float e = expf(g_scores[tid]);
    float sv = e;
#pragma unroll
    for (int off = 16; off; off >>= 1)
        sv += __shfl_xor_sync(0xffffffffu, sv, off);
    if ((tid & 31) == 0) red16[tid >> 5] = sv;
    __syncthreads();
    if (tid == 0) {
        float t = 0.f;
        for (int i = 0; i < 16; i++) t += red16[i];
        bsum = t;
    }
    __syncthreads();
    float a = e / bsum;
    attn_s[tid] = a;
    __syncthreads();

    // 4-instance h_bag partial
    if (tid < HID) {
        int n0 = b * 4;
        float acc = 0.f;
#pragma unroll
        for (int j = 0; j < 4; j++)
            acc += attn_s[n0 + j] * g_H[(n0 + j) * HID + tid];
        g_hbp[b * HID + tid] = acc;
    }
    __threadfence();
    __syncthreads();
    if (tid == 0) {
        unsigned ticket = atomicAdd(&g_ticket, 1u);
        islast = (ticket == NHB - 1);
    }
    __syncthreads();
    if (!islast) return;
    __threadfence();                    // acquire all partials

    // ---- final block: attn out, hb sum, logits ----
    out[NCLS + tid] = attn_s[tid];

    if (tid < HID) {
        float acc = 0.f;
#pragma unroll 16
        for (int bb = 0; bb < NHB; bb++)
            acc += g_hbp[bb * HID + tid];
        hbf[tid] = acc;
    }
    __syncthreads();

    int w = tid >> 5, lane = tid & 31;
    for (int t = w; t < NCLS; t += 16) {
        float part = 0.f;
#pragma unroll
        for (int c = lane; c < HID; c += 32)
            part += hbf[c] * __ldg(&fc_w[t * HID + c]);
#pragma unroll
        for (int off = 16; off; off >>= 1)
            part += __shfl_down_sync(0xffffffffu, part, off);
        if (lane == 0) out[t] = part + fc_b[t];
    }

    if (tid == 0) g_ticket = 0;         // reset for next graph replay
}

// ---------------- launch ------------------------------------------------------
extern "C" void kernel_launch(void* const* d_in, const int* in_sizes, int n_in,
                              void* d_out, int out_size) {
    const int*   char_ids = (const int*)d_in[0];
    const int*   pe1      = (const int*)d_in[1];
    const int*   pe2      = (const int*)d_in[2];
    const float* emb      = (const float*)d_in[3];
    const float* conv_w   = (const float*)d_in[4];
    const float* conv_b   = (const float*)d_in[5];
    const float* W_w      = (const float*)d_in[6];
    const float* W_b      = (const float*)d_in[7];
    const float* u_w      = (const float*)d_in[8];
    const float* fc_w     = (const float*)d_in[9];
    const float* fc_b     = (const float*)d_in[10];
    float* out = (float*)d_out;

    static bool attr_set = false;
    if (!attr_set) {
        cudaFuncSetAttribute(k1_hmma, cudaFuncAttributeMaxDynamicSharedMemorySize, K1_SMEM);
        attr_set = true;
    }

    k_prep<<<(2 * HID * EMB + 255) / 256, 256>>>(conv_w, W_w);
    k1_hmma<<<(VOCAB + 127) / 128, 256, K1_SMEM>>>(emb);
    k2_pool<<<N_INST / 2, 512>>>(char_ids, pe1, pe2, conv_b, W_b, u_w);
    k45<<<NHB, 512>>>(fc_w, fc_b, out);
}